// round 5
// baseline (speedup 1.0000x reference)
#include <cuda_runtime.h>
#include <mma.h>
#include <math.h>
#include <cstdint>

using namespace nvcuda;

#define BATCH 256
#define DIN   512
#define TSEQ  512
#define HID   1024
#define NG    4096      // 4 * HID, gate-interleaved
#define KTOT  1536      // HID + DIN
#define NCLS  1000

// ---------------- static device scratch (no allocations allowed) ----------------
__device__ float g_xT[(size_t)TSEQ * BATCH * DIN];   // x transposed to [T][B][D], tf32-rounded
__device__ float g_W[(size_t)KTOT * NG];             // [Wh; Wx] gate-interleaved, tf32-rounded
__device__ float g_bias[NG];
__device__ float g_h[2][(size_t)BATCH * HID];        // double-buffered hidden state (tf32-rounded)
__device__ float g_c[(size_t)BATCH * HID];           // cell state (full fp32)

__device__ __forceinline__ float rtf32(float v) {
    uint32_t u;
    asm("cvt.rna.tf32.f32 %0, %1;" : "=r"(u) : "f"(v));
    return __uint_as_float(u);
}

// ---------------- init: zero h[0] and c ----------------
__global__ void init_kernel() {
    size_t i = blockIdx.x * (size_t)blockDim.x + threadIdx.x;
    if (i < (size_t)BATCH * HID) {
        g_h[0][i] = 0.0f;
        g_c[i]    = 0.0f;
    }
}

// ---------------- pack weights: g_W[k][u*4+gate], gates ordered (g,f,i,o) ----------------
__global__ void pack_kernel(const float* __restrict__ Wfx, const float* __restrict__ Wfh,
                            const float* __restrict__ Wgx, const float* __restrict__ Wgh,
                            const float* __restrict__ Wix, const float* __restrict__ Wih,
                            const float* __restrict__ Wox, const float* __restrict__ Woh,
                            const float* __restrict__ bf,  const float* __restrict__ bg,
                            const float* __restrict__ bi,  const float* __restrict__ bo) {
    size_t idx = blockIdx.x * (size_t)blockDim.x + threadIdx.x;
    size_t total = (size_t)KTOT * NG;
    if (idx >= total) return;
    int e = (int)(idx % NG);
    int k = (int)(idx / NG);
    int u = e >> 2;
    int gate = e & 3;
    float v;
    if (k < HID) {
        const float* W = (gate == 0) ? Wgh : (gate == 1) ? Wfh : (gate == 2) ? Wih : Woh;
        v = W[(size_t)k * HID + u];
    } else {
        int d = k - HID;
        const float* W = (gate == 0) ? Wgx : (gate == 1) ? Wfx : (gate == 2) ? Wix : Wox;
        v = W[(size_t)d * HID + u];
    }
    g_W[idx] = rtf32(v);
    if (idx < NG) {
        const float* b = (gate == 0) ? bg : (gate == 1) ? bf : (gate == 2) ? bi : bo;
        g_bias[e] = b[u];
    }
}

// ---------------- transpose x [B,D,T] -> xT [T][B*D], tf32-rounded ----------------
__global__ void transpose_kernel(const float* __restrict__ x) {
    __shared__ float tile[32][33];
    int t0 = blockIdx.x * 32;
    int r0 = blockIdx.y * 32;
    int tx = threadIdx.x;
    int ty = threadIdx.y;     // blockDim = (32, 8)
#pragma unroll
    for (int i = 0; i < 32; i += 8)
        tile[ty + i][tx] = x[(size_t)(r0 + ty + i) * TSEQ + (t0 + tx)];
    __syncthreads();
#pragma unroll
    for (int i = 0; i < 32; i += 8)
        g_xT[(size_t)(t0 + ty + i) * (BATCH * DIN) + (r0 + tx)] = rtf32(tile[tx][ty + i]);
}

// ================= per-timestep fused GEMM + LSTM cell update =================
// Block tile 64(M) x 64(N), 256 threads = 8 warps, warp tile 32x16
// (2x1 of m16n16k8 tf32). 4-stage cp.async pipeline, KC=32, wait_group 2.
#define MB   64
#define NB   64
#define KC   32
#define LDA  36          // 32 + 4 pad
#define LDB  68          // 64 + 4 pad
#define LDCC 68
#define STAGES 4
#define ASTG (MB * LDA)  // 2304 floats per A stage
#define BSTG (KC * LDB)  // 2176 floats per B stage
#define NKIT (KTOT / KC) // 48

__device__ __forceinline__ void cp16(uint32_t dst_smem, const float* src) {
    asm volatile("cp.async.cg.shared.global [%0], [%1], 16;\n"
                 :: "r"(dst_smem), "l"(src));
}
__device__ __forceinline__ void cp_commit() {
    asm volatile("cp.async.commit_group;\n");
}
template <int N>
__device__ __forceinline__ void cp_wait() {
    asm volatile("cp.async.wait_group %0;\n" :: "n"(N));
}

__global__ void __launch_bounds__(256) step_kernel(int t) {
    __shared__ float smem[STAGES * (ASTG + BSTG)];   // 71,680 B; reused as C in epilogue
    float* sA = smem;                    // [STAGES][ASTG]
    float* sB = smem + STAGES * ASTG;    // [STAGES][BSTG]

    const int tid  = threadIdx.x;
    const int warp = tid >> 5;
    const int wm   = warp & 1;           // 0..1  (m offset wm*32)
    const int wn   = warp >> 1;          // 0..3  (n offset wn*16)
    const int b0   = blockIdx.y * MB;
    const int n0   = blockIdx.x * NB;

    const float* __restrict__ hin  = g_h[t & 1];
    float*       __restrict__ hout = g_h[(t + 1) & 1];
    const float* __restrict__ xTt  = g_xT + (size_t)t * (BATCH * DIN);

    uint32_t smem_base;
    {
        void* p = (void*)smem;
        asm("{ .reg .u64 tt; cvta.to.shared.u64 tt, %1; cvt.u32.u64 %0, tt; }"
            : "=r"(smem_base) : "l"(p));
    }

    auto stage = [&](int s, int kc) {
        // A tile: rows b0..b0+63, cols kc..kc+31 of [h | x] (chunks never straddle HID)
        const float* srcbase;
        int rstride;
        if (kc < HID) { srcbase = hin + (size_t)b0 * HID + kc;         rstride = HID; }
        else          { srcbase = xTt + (size_t)b0 * DIN + (kc - HID); rstride = DIN; }
        uint32_t adst = smem_base + (uint32_t)(s * ASTG) * 4u;
#pragma unroll
        for (int j = 0; j < 2; ++j) {
            int idx = j * 256 + tid;       // 512 float4 total
            int row = idx >> 3;            // 8 float4 per row
            int q   = idx & 7;
            cp16(adst + (uint32_t)(row * LDA + q * 4) * 4u,
                 srcbase + (size_t)row * rstride + q * 4);
        }
        // B tile: KC x 64 of packed weights
        uint32_t bdst = smem_base + (uint32_t)(STAGES * ASTG + s * BSTG) * 4u;
#pragma unroll
        for (int j = 0; j < 2; ++j) {
            int idx = j * 256 + tid;       // 512 float4 total
            int row = idx >> 4;            // 16 float4 per row
            int q   = idx & 15;
            cp16(bdst + (uint32_t)(row * LDB + q * 4) * 4u,
                 g_W + (size_t)(kc + row) * NG + n0 + q * 4);
        }
        cp_commit();
    };

    wmma::fragment<wmma::accumulator, 16, 16, 8, float> acc[2];
#pragma unroll
    for (int am = 0; am < 2; ++am)
        wmma::fill_fragment(acc[am], 0.0f);

    stage(0, 0);
    stage(1, KC);
    stage(2, 2 * KC);

    for (int it = 0; it < NKIT; ++it) {
        cp_wait<2>();
        __syncthreads();

        const int s = it % STAGES;
        const float* cA = sA + s * ASTG;
        const float* cB = sB + s * BSTG;

#pragma unroll
        for (int kk = 0; kk < KC; kk += 8) {
            wmma::fragment<wmma::matrix_a, 16, 16, 8, wmma::precision::tf32, wmma::row_major> af[2];
            wmma::fragment<wmma::matrix_b, 16, 16, 8, wmma::precision::tf32, wmma::row_major> bfr;
#pragma unroll
            for (int am = 0; am < 2; ++am)
                wmma::load_matrix_sync(af[am], cA + (wm * 32 + am * 16) * LDA + kk, LDA);
            wmma::load_matrix_sync(bfr, cB + kk * LDB + wn * 16, LDB);
            // operands pre-rounded to tf32 in gmem — no conversion needed here
#pragma unroll
            for (int am = 0; am < 2; ++am)
                wmma::mma_sync(acc[am], af[am], bfr, acc[am]);
        }

        // prefetch stage it+3 (always commit to keep group count consistent)
        if (it + 3 < NKIT) stage((it + 3) % STAGES, (it + 3) * KC);
        else               cp_commit();
    }

    // ---------------- epilogue: C -> gates -> cell update ----------------
    cp_wait<0>();
    __syncthreads();
    float* C = smem;    // 64 x LDCC floats = 17,408 B (fits in pipeline smem)
#pragma unroll
    for (int am = 0; am < 2; ++am)
        wmma::store_matrix_sync(C + (wm * 32 + am * 16) * LDCC + wn * 16,
                                acc[am], LDCC, wmma::mem_row_major);
    __syncthreads();

    const int u0 = n0 >> 2;   // 16 hidden units per block
#pragma unroll
    for (int p = 0; p < 4; ++p) {
        int e = p * 256 + tid;  // 0..1023 = r*16 + u
        int r = e >> 4;
        int u = e & 15;
        float gg = tanhf(C[r * LDCC + u * 4 + 0] + g_bias[n0 + u * 4 + 0]);
        float ff = tanhf(C[r * LDCC + u * 4 + 1] + g_bias[n0 + u * 4 + 1]);
        float ii = tanhf(C[r * LDCC + u * 4 + 2] + g_bias[n0 + u * 4 + 2]);
        float oo = tanhf(C[r * LDCC + u * 4 + 3] + g_bias[n0 + u * 4 + 3]);
        size_t cidx = (size_t)(b0 + r) * HID + (u0 + u);
        float c = gg * ii + g_c[cidx] * ff;
        g_c[cidx]  = c;
        hout[cidx] = rtf32(tanhf(c) * oo);
    }
}

// ---------------- head: softmax(h @ W_ph + b_p) ----------------
__global__ void __launch_bounds__(256) head_kernel(const float* __restrict__ Wph,
                                                   const float* __restrict__ bp,
                                                   float* __restrict__ out) {
    __shared__ float hs[HID];
    __shared__ float lg[NCLS];
    __shared__ float red[256];
    int b   = blockIdx.x;
    int tid = threadIdx.x;
    const float* h = g_h[0];   // after 512 steps, final h lives in buffer 0

    for (int i = tid; i < HID; i += 256)
        hs[i] = h[(size_t)b * HID + i];
    __syncthreads();

    for (int c = tid; c < NCLS; c += 256) {
        float acc = bp[c];
#pragma unroll 8
        for (int k = 0; k < HID; ++k)
            acc += hs[k] * Wph[(size_t)k * NCLS + c];
        lg[c] = acc;
    }
    __syncthreads();

    float m = -1e30f;
    for (int c = tid; c < NCLS; c += 256) m = fmaxf(m, lg[c]);
    red[tid] = m;
    __syncthreads();
    for (int s = 128; s > 0; s >>= 1) {
        if (tid < s) red[tid] = fmaxf(red[tid], red[tid + s]);
        __syncthreads();
    }
    m = red[0];
    __syncthreads();

    float sum = 0.0f;
    for (int c = tid; c < NCLS; c += 256) {
        float ex = expf(lg[c] - m);
        lg[c] = ex;
        sum += ex;
    }
    red[tid] = sum;
    __syncthreads();
    for (int s = 128; s > 0; s >>= 1) {
        if (tid < s) red[tid] += red[tid + s];
        __syncthreads();
    }
    float inv = 1.0f / red[0];
    for (int c = tid; c < NCLS; c += 256)
        out[(size_t)b * NCLS + c] = lg[c] * inv;
}

// ---------------- launch ----------------
extern "C" void kernel_launch(void* const* d_in, const int* in_sizes, int n_in,
                              void* d_out, int out_size) {
    (void)in_sizes; (void)n_in; (void)out_size;
    const float* x   = (const float*)d_in[0];
    const float* Wfx = (const float*)d_in[1];
    const float* Wfh = (const float*)d_in[2];
    const float* Wgx = (const float*)d_in[3];
    const float* Wgh = (const float*)d_in[4];
    const float* Wix = (const float*)d_in[5];
    const float* Wih = (const float*)d_in[6];
    const float* Wox = (const float*)d_in[7];
    const float* Woh = (const float*)d_in[8];
    const float* Wph = (const float*)d_in[9];
    const float* bf  = (const float*)d_in[10];
    const float* bg  = (const float*)d_in[11];
    const float* bi  = (const float*)d_in[12];
    const float* bo  = (const float*)d_in[13];
    const float* bp  = (const float*)d_in[14];
    float* out = (float*)d_out;

    init_kernel<<<(BATCH * HID + 255) / 256, 256>>>();

    size_t packN = (size_t)KTOT * NG;
    pack_kernel<<<(unsigned)((packN + 255) / 256), 256>>>(Wfx, Wfh, Wgx, Wgh,
                                                          Wix, Wih, Wox, Woh,
                                                          bf, bg, bi, bo);

    transpose_kernel<<<dim3(TSEQ / 32, (BATCH * DIN) / 32), dim3(32, 8)>>>(x);

    for (int t = 0; t < TSEQ; ++t)
        step_kernel<<<dim3(NG / NB, BATCH / MB), 256>>>(t);

    head_kernel<<<BATCH, 256>>>(Wph, bp, out);
}

// round 7
// speedup vs baseline: 1.1368x; 1.1368x over previous
#include <cuda_runtime.h>
#include <mma.h>
#include <math.h>
#include <cstdint>

using namespace nvcuda;

#define BATCH 256
#define DIN   512
#define TSEQ  512
#define HID   1024
#define NG    4096      // 4 * HID, gate-interleaved
#define KTOT  1536      // HID + DIN
#define NCLS  1000

#define NBLK  128       // persistent blocks, one per SM, 32 gate-cols each
#define NB    32
#define WLD   1538      // sW column stride (k-contiguous), 1538%32==2 -> conflict-free
#define KC    16        // k-chunk per pipeline stage
#define NKIT  (KTOT / KC)   // 96
#define ALD   16            // A stage row stride (64 B, 16B-aligned for cp.async)
#define AWSZ  (32 * ALD)    // per-warp A stage: 512 floats
#define SMEM_FLOATS (NB * WLD + 8 * 2 * AWSZ)   // 49216 + 8192 = 57408
#define SMEM_BYTES  (SMEM_FLOATS * 4)           // 229,632 B  (< 232,448 limit)

// ---------------- static device scratch ----------------
__device__ float g_xT[(size_t)TSEQ * BATCH * DIN];   // x transposed [T][B][D], tf32-rounded
__device__ float g_W[(size_t)KTOT * NG];             // [Wh; Wx] gate-interleaved, tf32-rounded
__device__ float g_bias[NG];
__device__ float g_h[2][(size_t)BATCH * HID];        // double-buffered hidden state
__device__ float g_c[(size_t)BATCH * HID];           // cell state
__device__ unsigned g_arrive;
__device__ unsigned g_release;

__device__ __forceinline__ float rtf32(float v) {
    uint32_t u;
    asm("cvt.rna.tf32.f32 %0, %1;" : "=r"(u) : "f"(v));
    return __uint_as_float(u);
}
__device__ __forceinline__ unsigned ld_acquire(const unsigned* p) {
    unsigned v;
    asm volatile("ld.acquire.gpu.global.u32 %0, [%1];" : "=r"(v) : "l"(p));
    return v;
}
__device__ __forceinline__ void st_release(unsigned* p, unsigned v) {
    asm volatile("st.release.gpu.global.u32 [%0], %1;" :: "l"(p), "r"(v));
}
__device__ __forceinline__ void cp16(uint32_t dst_smem, const float* src) {
    asm volatile("cp.async.cg.shared.global [%0], [%1], 16;\n" :: "r"(dst_smem), "l"(src));
}
__device__ __forceinline__ void cp_commit() {
    asm volatile("cp.async.commit_group;\n");
}
template <int N>
__device__ __forceinline__ void cp_wait() {
    asm volatile("cp.async.wait_group %0;\n" :: "n"(N));
}

// ---------------- init ----------------
__global__ void init_kernel() {
    size_t i = blockIdx.x * (size_t)blockDim.x + threadIdx.x;
    if (i < (size_t)BATCH * HID) {
        g_h[0][i] = 0.0f;
        g_c[i]    = 0.0f;
    }
    if (i == 0) { g_arrive = 0u; g_release = 0u; }
}

// ---------------- pack weights: g_W[k][u*4+gate], gates (g,f,i,o), tf32-rounded ----------------
__global__ void pack_kernel(const float* __restrict__ Wfx, const float* __restrict__ Wfh,
                            const float* __restrict__ Wgx, const float* __restrict__ Wgh,
                            const float* __restrict__ Wix, const float* __restrict__ Wih,
                            const float* __restrict__ Wox, const float* __restrict__ Woh,
                            const float* __restrict__ bf,  const float* __restrict__ bg,
                            const float* __restrict__ bi,  const float* __restrict__ bo) {
    size_t idx = blockIdx.x * (size_t)blockDim.x + threadIdx.x;
    size_t total = (size_t)KTOT * NG;
    if (idx >= total) return;
    int e = (int)(idx % NG);
    int k = (int)(idx / NG);
    int u = e >> 2;
    int gate = e & 3;
    float v;
    if (k < HID) {
        const float* W = (gate == 0) ? Wgh : (gate == 1) ? Wfh : (gate == 2) ? Wih : Woh;
        v = W[(size_t)k * HID + u];
    } else {
        int d = k - HID;
        const float* W = (gate == 0) ? Wgx : (gate == 1) ? Wfx : (gate == 2) ? Wix : Wox;
        v = W[(size_t)d * HID + u];
    }
    g_W[idx] = rtf32(v);
    if (idx < NG) {
        const float* b = (gate == 0) ? bg : (gate == 1) ? bf : (gate == 2) ? bi : bo;
        g_bias[e] = b[u];
    }
}

// ---------------- transpose x [B,D,T] -> xT [T][B*D], tf32-rounded ----------------
__global__ void transpose_kernel(const float* __restrict__ x) {
    __shared__ float tile[32][33];
    int t0 = blockIdx.x * 32;
    int r0 = blockIdx.y * 32;
    int tx = threadIdx.x;
    int ty = threadIdx.y;     // blockDim = (32, 8)
#pragma unroll
    for (int i = 0; i < 32; i += 8)
        tile[ty + i][tx] = x[(size_t)(r0 + ty + i) * TSEQ + (t0 + tx)];
    __syncthreads();
#pragma unroll
    for (int i = 0; i < 32; i += 8)
        g_xT[(size_t)(t0 + ty + i) * (BATCH * DIN) + (r0 + tx)] = rtf32(tile[tx][ty + i]);
}

// ================= persistent LSTM kernel =================
// 128 blocks x 256 threads. Block owns gate-columns n0..n0+31 (units u0..u0+7)
// with its W slice resident in SMEM (col-major, ld=WLD). 8 warps each own a
// 32-row batch slab; per-warp double-buffered cp.async A staging, no block
// barriers inside the k-loop. Grid softbarrier between timesteps.
__global__ void __launch_bounds__(256) lstm_persistent_kernel() {
    extern __shared__ float smem[];
    float* sW   = smem;                       // [NB][WLD]  (n-major, k contiguous)
    float* sAll = smem + NB * WLD;            // 8 warps x 2 stages x AWSZ

    const int tid  = threadIdx.x;
    const int warp = tid >> 5;
    const int lane = tid & 31;
    const int n0   = blockIdx.x * NB;
    const int m0   = warp * 32;               // this warp's batch rows
    float* sA = sAll + warp * (2 * AWSZ);

    uint32_t sA_base;
    {
        void* p = (void*)sA;
        asm("{ .reg .u64 tt; cvta.to.shared.u64 tt, %1; cvt.u32.u64 %0, tt; }"
            : "=r"(sA_base) : "l"(p));
    }

    // ---- one-time: load W slice into SMEM: sW[n][k] = g_W[k][n0+n] ----
    for (int idx = tid; idx < KTOT * NB; idx += 256) {
        int k = idx >> 5;
        int n = idx & 31;
        sW[n * WLD + k] = g_W[(size_t)k * NG + n0 + n];
    }
    // epilogue constants per lane: unit u = lane&7, 4 gate biases
    const int eu   = lane & 7;
    const int ersb = lane >> 3;
    const float bias_g = g_bias[n0 + eu * 4 + 0];
    const float bias_f = g_bias[n0 + eu * 4 + 1];
    const float bias_i = g_bias[n0 + eu * 4 + 2];
    const float bias_o = g_bias[n0 + eu * 4 + 3];
    const int u0 = n0 >> 2;
    __syncthreads();

    for (int t = 0; t < TSEQ; ++t) {
        const float* __restrict__ hin  = g_h[t & 1];
        float*       __restrict__ hout = g_h[(t + 1) & 1];
        const float* __restrict__ xTt  = g_xT + (size_t)t * (BATCH * DIN);

        // per-warp stage: 32 rows x KC cols, 4 cp.async(16B) per lane
        auto stage = [&](int s, int kc) {
            const float* srcbase;
            int rstride;
            if (kc < HID) { srcbase = hin + (size_t)m0 * HID + kc;         rstride = HID; }
            else          { srcbase = xTt + (size_t)m0 * DIN + (kc - HID); rstride = DIN; }
            uint32_t dst0 = sA_base + (uint32_t)(s * AWSZ) * 4u;
#pragma unroll
            for (int j = 0; j < 4; ++j) {
                int idx = j * 32 + lane;      // 128 float4 total
                int row = idx >> 2;
                int q   = idx & 3;
                cp16(dst0 + (uint32_t)(row * ALD + q * 4) * 4u,
                     srcbase + (size_t)row * rstride + q * 4);
            }
            cp_commit();
        };

        wmma::fragment<wmma::accumulator, 16, 16, 8, float> acc[2][2];
#pragma unroll
        for (int am = 0; am < 2; ++am)
#pragma unroll
            for (int bn = 0; bn < 2; ++bn)
                wmma::fill_fragment(acc[am][bn], 0.0f);

        stage(0, 0);
        stage(1, KC);

        for (int it = 0; it < NKIT; ++it) {
            cp_wait<1>();
            __syncwarp();
            const int s = it & 1;
            const float* cA = sA + s * AWSZ;
            const int kc = it * KC;

#pragma unroll
            for (int kk = 0; kk < KC; kk += 8) {
                wmma::fragment<wmma::matrix_a, 16, 16, 8, wmma::precision::tf32, wmma::row_major> af[2];
                wmma::fragment<wmma::matrix_b, 16, 16, 8, wmma::precision::tf32, wmma::col_major> bfr[2];
#pragma unroll
                for (int am = 0; am < 2; ++am)
                    wmma::load_matrix_sync(af[am], cA + (am * 16) * ALD + kk, ALD);
#pragma unroll
                for (int bn = 0; bn < 2; ++bn)
                    wmma::load_matrix_sync(bfr[bn], sW + (bn * 16) * WLD + kc + kk, WLD);
#pragma unroll
                for (int am = 0; am < 2; ++am)
#pragma unroll
                    for (int bn = 0; bn < 2; ++bn)
                        wmma::mma_sync(acc[am][bn], af[am], bfr[bn], acc[am][bn]);
            }

            // prefetch chunk it+2 into the stage we just consumed
            if (it + 2 < NKIT) stage(s, (it + 2) * KC);
            else               cp_commit();   // keep group count consistent
        }
        cp_wait<0>();
        __syncwarp();

        // ---- epilogue (warp-local): C tile 32x32 -> 8 units x 32 rows ----
        float* sC = sA;   // reuse this warp's 1024-float staging area (32*32 fits exactly)
#pragma unroll
        for (int am = 0; am < 2; ++am)
#pragma unroll
            for (int bn = 0; bn < 2; ++bn)
                wmma::store_matrix_sync(sC + (am * 16) * 32 + bn * 16,
                                        acc[am][bn], 32, wmma::mem_row_major);
        __syncwarp();

#pragma unroll
        for (int j = 0; j < 8; ++j) {
            int r = j * 4 + ersb;             // 0..31
            float gg = tanhf(sC[r * 32 + eu * 4 + 0] + bias_g);
            float ff = tanhf(sC[r * 32 + eu * 4 + 1] + bias_f);
            float ii = tanhf(sC[r * 32 + eu * 4 + 2] + bias_i);
            float oo = tanhf(sC[r * 32 + eu * 4 + 3] + bias_o);
            size_t cidx = (size_t)(m0 + r) * HID + (u0 + eu);
            float c = gg * ii + g_c[cidx] * ff;
            g_c[cidx]  = c;
            hout[cidx] = rtf32(tanhf(c) * oo);
        }

        // ---- grid softbarrier (monotonic counter, release/acquire) ----
        __threadfence();
        __syncthreads();
        if (tid == 0) {
            unsigned cnt    = atomicAdd(&g_arrive, 1u) + 1u;
            unsigned target = (unsigned)NBLK * (unsigned)(t + 1);
            if (cnt == target) {
                __threadfence();
                st_release(&g_release, (unsigned)(t + 1));
            } else {
                while (ld_acquire(&g_release) < (unsigned)(t + 1)) { }
            }
        }
        __syncthreads();
    }
}

// ---------------- head: softmax(h @ W_ph + b_p) ----------------
__global__ void __launch_bounds__(256) head_kernel(const float* __restrict__ Wph,
                                                   const float* __restrict__ bp,
                                                   float* __restrict__ out) {
    __shared__ float hs[HID];
    __shared__ float lg[NCLS];
    __shared__ float red[256];
    int b   = blockIdx.x;
    int tid = threadIdx.x;
    const float* h = g_h[0];   // after 512 steps, final h lives in buffer 0

    for (int i = tid; i < HID; i += 256)
        hs[i] = h[(size_t)b * HID + i];
    __syncthreads();

    for (int c = tid; c < NCLS; c += 256) {
        float acc = bp[c];
#pragma unroll 8
        for (int k = 0; k < HID; ++k)
            acc += hs[k] * Wph[(size_t)k * NCLS + c];
        lg[c] = acc;
    }
    __syncthreads();

    float m = -1e30f;
    for (int c = tid; c < NCLS; c += 256) m = fmaxf(m, lg[c]);
    red[tid] = m;
    __syncthreads();
    for (int s = 128; s > 0; s >>= 1) {
        if (tid < s) red[tid] = fmaxf(red[tid], red[tid + s]);
        __syncthreads();
    }
    m = red[0];
    __syncthreads();

    float sum = 0.0f;
    for (int c = tid; c < NCLS; c += 256) {
        float ex = expf(lg[c] - m);
        lg[c] = ex;
        sum += ex;
    }
    red[tid] = sum;
    __syncthreads();
    for (int s = 128; s > 0; s >>= 1) {
        if (tid < s) red[tid] += red[tid + s];
        __syncthreads();
    }
    float inv = 1.0f / red[0];
    for (int c = tid; c < NCLS; c += 256)
        out[(size_t)b * NCLS + c] = lg[c] * inv;
}

// ---------------- launch ----------------
extern "C" void kernel_launch(void* const* d_in, const int* in_sizes, int n_in,
                              void* d_out, int out_size) {
    (void)in_sizes; (void)n_in; (void)out_size;
    const float* x   = (const float*)d_in[0];
    const float* Wfx = (const float*)d_in[1];
    const float* Wfh = (const float*)d_in[2];
    const float* Wgx = (const float*)d_in[3];
    const float* Wgh = (const float*)d_in[4];
    const float* Wix = (const float*)d_in[5];
    const float* Wih = (const float*)d_in[6];
    const float* Wox = (const float*)d_in[7];
    const float* Woh = (const float*)d_in[8];
    const float* Wph = (const float*)d_in[9];
    const float* bf  = (const float*)d_in[10];
    const float* bg  = (const float*)d_in[11];
    const float* bi  = (const float*)d_in[12];
    const float* bo  = (const float*)d_in[13];
    const float* bp  = (const float*)d_in[14];
    float* out = (float*)d_out;

    cudaFuncSetAttribute(lstm_persistent_kernel,
                         cudaFuncAttributeMaxDynamicSharedMemorySize, SMEM_BYTES);

    init_kernel<<<(BATCH * HID + 255) / 256, 256>>>();

    size_t packN = (size_t)KTOT * NG;
    pack_kernel<<<(unsigned)((packN + 255) / 256), 256>>>(Wfx, Wfh, Wgx, Wgh,
                                                          Wix, Wih, Wox, Woh,
                                                          bf, bg, bi, bo);

    transpose_kernel<<<dim3(TSEQ / 32, (BATCH * DIN) / 32), dim3(32, 8)>>>(x);

    lstm_persistent_kernel<<<NBLK, 256, SMEM_BYTES>>>();

    head_kernel<<<BATCH, 256>>>(Wph, bp, out);
}